// round 12
// baseline (speedup 1.0000x reference)
#include <cuda_runtime.h>
#include <math.h>

#define NA 48
#define NS 4
#define NSHFR 16
#define NSHFA 4
#define NSHFZ 8
#define RAD_FEAT (NS * NSHFR)                     // 64
#define ANG_SUB (NSHFA * NSHFZ)                   // 32
#define NPAIRS_SP (NS * (NS + 1) / 2)             // 10
#define ANG_FEAT (NPAIRS_SP * ANG_SUB)            // 320
#define AEV_LEN (RAD_FEAT + ANG_FEAT)             // 384
#define RCR_F 5.2f
#define RCA_F 3.5f
#define PI_F 3.14159265358979323846f
#define NTHR 128
#define NWARP 4
#define NVW 8            // virtual warps = NWARP * 2 sets
#define CHUNK 256        // pairs per chunk (2 per thread)

__device__ __forceinline__ int triu_idx(int a, int b) {
    int lo = min(a, b), hi = max(a, b);
    return lo * NS - (lo * (lo - 1)) / 2 + (hi - lo);
}

__device__ __forceinline__ float pow_zeta(float x, float zeta, bool z32) {
    if (z32) {
        float y = x * x;  // ^2
        y = y * y;        // ^4
        y = y * y;        // ^8
        y = y * y;        // ^16
        return y * y;     // ^32
    }
    return __powf(x, zeta);
}

// decode pair index p -> (a,b), a<b among n items
__device__ __forceinline__ void decode_pair(int p, int n, int& a, int& b) {
    float fn = (float)n;
    float tt = 2.0f * fn - 1.0f;
    a = (int)(0.5f * (tt - sqrtf(fmaxf(tt * tt - 8.0f * (float)p, 0.0f))));
    while (a > 0 && p < a * n - (a * (a + 1)) / 2) a--;
    while (p >= (a + 1) * n - ((a + 1) * (a + 2)) / 2) a++;
    b = p - (a * n - (a * (a + 1)) / 2) + a + 1;
}

__global__ __launch_bounds__(NTHR, 12)
void aev_kernel(const float* __restrict__ coords,   // (M, A, 3)
                const float* __restrict__ gEtaR,
                const float* __restrict__ gShfR,    // (16,)
                const float* __restrict__ gEtaA,
                const float* __restrict__ gZeta,
                const float* __restrict__ gShfA,    // (4,)
                const float* __restrict__ gShfZ,    // (8,)
                const int*   __restrict__ species,  // (M, A)
                float* __restrict__ out)            // (M, A, 384)
{
    const int i = blockIdx.x;
    const int m = blockIdx.y;
    const int tid = threadIdx.x;
    const int lane = tid & 31;
    const int wid = tid >> 5;
    const unsigned ltm = (1u << lane) - 1u;

    __shared__ float sx[NA], sy[NA], sz[NA];
    __shared__ int   ssp[NA];
    __shared__ float shfr[NSHFR], shfa[NSHFA];
    __shared__ float cshfz[NSHFZ], sshfz[NSHFZ];
    __shared__ float s_etaR, s_etaA, s_zeta;
    // radial list, sorted by species
    __shared__ float dR[NA], qfcR[NA];
    __shared__ int   cntRspw[2][NS];
    __shared__ int   rstart[NS + 1];
    // angular list (ballot order)
    __shared__ float avx[NA], avy[NA], avz[NA], ad[NA], afc[NA];
    __shared__ int   asp[NA];
    __shared__ int   wcntA[2];
    // per-chunk pair data (stored pre-sorted by pidx)
    __shared__ float f1s[CHUNK * 9];          // padded stride 9
    __shared__ float f2s[CHUNK * 5];          // padded stride 5
    __shared__ int   cntPw[NVW][NPAIRS_SP];   // becomes exclusive vwarp-prefix
    __shared__ int   pstart[NPAIRS_SP + 1];
    __shared__ float radout[RAD_FEAT];

    // ---- phase 0: load ----
    if (tid < NA) {
        const float* c = coords + ((size_t)m * NA + tid) * 3;
        sx[tid] = c[0];
        sy[tid] = c[1];
        sz[tid] = c[2];
        ssp[tid] = species[(size_t)m * NA + tid];
    }
    if (tid < NSHFR) shfr[tid] = gShfR[tid];
    if (tid < NSHFA) shfa[tid] = gShfA[tid];
    if (tid < NSHFZ) {
        float z = gShfZ[tid];
        cshfz[tid] = cosf(z);
        sshfz[tid] = sinf(z);
    }
    if (tid == 0) {
        s_etaR = gEtaR[0];
        s_etaA = gEtaA[0];
        s_zeta = gZeta[0];
    }
    if (tid < 2 * NS) ((int*)cntRspw)[tid] = 0;
    if (tid < 2) wcntA[tid] = 0;
    __syncthreads();

    const float cx = sx[i], cy = sy[i], cz = sz[i];
    const float etaR = s_etaR, etaA = s_etaA, zeta = s_zeta;
    const bool z32 = (zeta == 32.0f);

    // ---- phase 1: deterministic compaction (warps 0,1 cover j = 0..47) ----
    if (wid < 2) {
        int j = tid;
        float dx = 0.f, dy = 0.f, dz = 0.f, d = 1e9f;
        bool valid = (j < NA) && (j != i);
        int sp = 0;
        if (valid) {
            dx = sx[j] - cx;
            dy = sy[j] - cy;
            dz = sz[j] - cz;
            d = sqrtf(dx * dx + dy * dy + dz * dz);
            sp = ssp[j];
        }
        bool inR = valid && (d <= RCR_F);
        bool inA = valid && (d <= RCA_F);
        unsigned ballR = __ballot_sync(0xffffffffu, inR);
        unsigned ballA = __ballot_sync(0xffffffffu, inA);

        unsigned mspR = __match_any_sync(0xffffffffu, inR ? sp : (NS + lane)) & ballR;
        int rankR = __popc(mspR & ltm);
        if (inR && (lane == (__ffs(mspR) - 1)))
            cntRspw[wid][sp] = __popc(mspR);

        int rankA = __popc(ballA & ltm);
        if (lane == 0) wcntA[wid] = __popc(ballA);
        __syncthreads();

        if (tid <= NS) {
            int acc = 0;
            for (int s = 0; s < tid; s++)
                acc += cntRspw[0][s] + cntRspw[1][s];
            rstart[tid] = acc;
        }
        __syncthreads();

        if (inR) {
            int off = rstart[sp] + rankR;
            if (wid == 1) off += cntRspw[0][sp];
            dR[off] = d;
            qfcR[off] = 0.25f * (0.5f * __cosf(d * (PI_F / RCR_F)) + 0.5f);
        }
        if (inA) {
            int off = rankA;
            if (wid == 1) off += wcntA[0];
            avx[off] = dx; avy[off] = dy; avz[off] = dz;
            ad[off] = d;
            afc[off] = 0.5f * __cosf(d * (PI_F / RCA_F)) + 0.5f;
            asp[off] = sp;
        }
    } else {
        __syncthreads();
        __syncthreads();
    }
    __syncthreads();
    const int nA = wcntA[0] + wcntA[1];

    // ---- phase 2: radial, feature-parallel over species buckets (warps 0,1) ----
    if (tid < RAD_FEAT) {
        int sp = tid >> 4;
        float sk = shfr[tid & 15];
        float acc = 0.0f;
        int jb = rstart[sp], je = rstart[sp + 1];
        for (int j = jb; j < je; j++) {
            float t = dR[j] - sk;
            acc += qfcR[j] * __expf(-etaR * t * t);
        }
        radout[tid] = acc;
    }

    // ---- phase 3: angular pairs, 2 pairs/thread per chunk, pre-sorted by pidx ----
    const int npairs = nA * (nA - 1) / 2;
    float acc0 = 0.f, acc1 = 0.f, acc2 = 0.f;

    for (int base = 0; base < npairs; base += CHUNK) {
        if (base > 0) __syncthreads();   // protect previous chunk's scan

        int p0 = base + tid;
        int p1 = base + 128 + tid;
        bool v0 = (p0 < npairs);
        bool v1 = (p1 < npairs);

        int a0 = 0, b0 = 0, a1 = 0, b1 = 0;
        int pidx0 = NPAIRS_SP + lane;    // per-lane sentinels (never match a bucket)
        int pidx1 = NPAIRS_SP + lane;
        if (v0) {
            decode_pair(p0, nA, a0, b0);
            pidx0 = triu_idx(asp[a0], asp[b0]);
        }
        if (v1) {
            decode_pair(p1, nA, a1, b1);
            pidx1 = triu_idx(asp[a1], asp[b1]);
        }

        // histogram over 8 virtual warps (wid*2 + set); ranks via match
        unsigned msk0 = __match_any_sync(0xffffffffu, pidx0);
        int rank0 = __popc(msk0 & ltm);
        unsigned msk1 = __match_any_sync(0xffffffffu, pidx1);
        int rank1 = __popc(msk1 & ltm);
        #pragma unroll
        for (int k = 0; k < NPAIRS_SP; k++) {
            unsigned bk0 = __ballot_sync(0xffffffffu, pidx0 == k);
            unsigned bk1 = __ballot_sync(0xffffffffu, pidx1 == k);
            if (lane == k) {
                cntPw[wid * 2][k] = __popc(bk0);
                cntPw[wid * 2 + 1][k] = __popc(bk1);
            }
        }
        __syncthreads();

        // warp 0: exclusive scan of cntPw over virtual warps, then pstart
        if (wid == 0) {
            int tot = 0;
            if (lane < NPAIRS_SP) {
                int acc = 0;
                #pragma unroll
                for (int w = 0; w < NVW; w++) {
                    int c = cntPw[w][lane];
                    cntPw[w][lane] = acc;
                    acc += c;
                }
                tot = acc;
            }
            int scan = tot;
            #pragma unroll
            for (int o = 1; o < 16; o <<= 1) {
                int v = __shfl_up_sync(0xffffffffu, scan, o);
                if (lane >= o) scan += v;
            }
            if (lane < NPAIRS_SP) pstart[lane + 1] = scan;
            if (lane == 0) pstart[0] = 0;
        }
        __syncthreads();

        // compute + store both pairs (independent chains -> ILP)
        #pragma unroll
        for (int set = 0; set < 2; set++) {
            bool v = set ? v1 : v0;
            if (!v) continue;
            int a = set ? a1 : a0;
            int b = set ? b1 : b0;
            int px = set ? pidx1 : pidx0;
            int rk = set ? rank1 : rank0;
            int slot = pstart[px] + cntPw[wid * 2 + set][px] + rk;

            float d1 = ad[a], d2 = ad[b];
            float dot = avx[a] * avx[b] + avy[a] * avy[b] + avz[a] * avz[b];
            float cosv = 0.95f * __fdividef(dot, fmaxf(d1, 1e-8f) * fmaxf(d2, 1e-8f));
            float sinv = sqrtf(fmaxf(1.0f - cosv * cosv, 0.0f));
            float dm = 0.5f * (d1 + d2);
            float fcj2 = 2.0f * afc[a] * afc[b];

            #pragma unroll
            for (int t = 0; t < NSHFZ; t++) {
                float c = cosv * cshfz[t] + sinv * sshfz[t];
                float bse = 0.5f * (1.0f + c);
                f1s[slot * 9 + t] = pow_zeta(bse, zeta, z32) * fcj2;
            }
            #pragma unroll
            for (int s = 0; s < NSHFA; s++) {
                float dd = dm - shfa[s];
                f2s[slot * 5 + s] = __expf(-etaA * dd * dd);
            }
        }
        __syncthreads();

        // feature accumulation: warp w scans bucket w, then 4+w; warps 0,1: 8,9
        {
            int s = (tid >> 3) & 3, t = tid & 7;
            int qb = pstart[wid], qe = pstart[wid + 1];
            for (int q = qb; q < qe; q++)
                acc0 += f1s[q * 9 + t] * f2s[q * 5 + s];
        }
        {
            int pf = 4 + wid, s = (tid >> 3) & 3, t = tid & 7;
            int qb = pstart[pf], qe = pstart[pf + 1];
            for (int q = qb; q < qe; q++)
                acc1 += f1s[q * 9 + t] * f2s[q * 5 + s];
        }
        if (tid < 64) {   // buckets 8,9 -> warps 0,1
            int pf = 8 + (tid >> 5), s = (tid >> 3) & 3, t = tid & 7;
            int qb = pstart[pf], qe = pstart[pf + 1];
            for (int q = qb; q < qe; q++)
                acc2 += f1s[q * 9 + t] * f2s[q * 5 + s];
        }
    }

    // ---- write out (no final sync needed: each thread reads its own data) ----
    float* o = out + ((size_t)m * NA + i) * AEV_LEN;
    if (tid < RAD_FEAT) o[tid] = radout[tid];
    o[RAD_FEAT + tid] = acc0;
    o[RAD_FEAT + 128 + tid] = acc1;
    if (tid < 64) o[RAD_FEAT + 256 + tid] = acc2;
}

extern "C" void kernel_launch(void* const* d_in, const int* in_sizes, int n_in,
                              void* d_out, int out_size) {
    const float* coords = (const float*)d_in[0];
    const float* EtaR   = (const float*)d_in[1];
    const float* ShfR   = (const float*)d_in[2];
    const float* EtaA   = (const float*)d_in[3];
    const float* Zeta   = (const float*)d_in[4];
    const float* ShfA   = (const float*)d_in[5];
    const float* ShfZ   = (const float*)d_in[6];
    const int*   spec   = (const int*)d_in[7];
    float* out = (float*)d_out;

    int MA = in_sizes[7];
    int M = MA / NA;

    dim3 grid(NA, M);
    aev_kernel<<<grid, NTHR>>>(coords, EtaR, ShfR, EtaA, Zeta, ShfA, ShfZ, spec, out);
}

// round 13
// speedup vs baseline: 1.0950x; 1.0950x over previous
#include <cuda_runtime.h>
#include <math.h>

#define NA 48
#define NS 4
#define NSHFR 16
#define NSHFA 4
#define NSHFZ 8
#define RAD_FEAT (NS * NSHFR)                     // 64
#define ANG_SUB (NSHFA * NSHFZ)                   // 32
#define NPAIRS_SP (NS * (NS + 1) / 2)             // 10
#define ANG_FEAT (NPAIRS_SP * ANG_SUB)            // 320
#define AEV_LEN (RAD_FEAT + ANG_FEAT)             // 384
#define RCR_F 5.2f
#define RCA_F 3.5f
#define PI_F 3.14159265358979323846f
#define NTHR 128
#define NWARP 4
#define CHUNK 128
#define FULLM 0xffffffffu

__device__ __forceinline__ int triu_idx(int a, int b) {
    int lo = min(a, b), hi = max(a, b);
    return lo * NS - (lo * (lo - 1)) / 2 + (hi - lo);
}

__device__ __forceinline__ float pow_zeta(float x, float zeta, bool z32) {
    if (z32) {
        float y = x * x;  // ^2
        y = y * y;        // ^4
        y = y * y;        // ^8
        y = y * y;        // ^16
        return y * y;     // ^32
    }
    return __powf(x, zeta);
}

// decode pair index p -> (a,b), a<b among n items
__device__ __forceinline__ void decode_pair(int p, int n, int& a, int& b) {
    float fn = (float)n;
    float tt = 2.0f * fn - 1.0f;
    a = (int)(0.5f * (tt - sqrtf(fmaxf(tt * tt - 8.0f * (float)p, 0.0f))));
    while (a > 0 && p < a * n - (a * (a + 1)) / 2) a--;
    while (p >= (a + 1) * n - ((a + 1) * (a + 2)) / 2) a++;
    b = p - (a * n - (a * (a + 1)) / 2) + a + 1;
}

__global__ __launch_bounds__(NTHR, 12)
void aev_kernel(const float* __restrict__ coords,   // (M, A, 3)
                const float* __restrict__ gEtaR,
                const float* __restrict__ gShfR,    // (16,)
                const float* __restrict__ gEtaA,
                const float* __restrict__ gZeta,
                const float* __restrict__ gShfA,    // (4,)
                const float* __restrict__ gShfZ,    // (8,)
                const int*   __restrict__ species,  // (M, A)
                float* __restrict__ out)            // (M, A, 384)
{
    const int i = blockIdx.x;
    const int m = blockIdx.y;
    const int tid = threadIdx.x;
    const int lane = tid & 31;
    const int wid = tid >> 5;
    const unsigned ltm = (1u << lane) - 1u;

    __shared__ float scrd[NA * 3];                 // flat xyz
    __shared__ int   ssp[NA];
    __shared__ float shfr[NSHFR], shfa[NSHFA];
    __shared__ float cshfz[NSHFZ], sshfz[NSHFZ];
    __shared__ float s_etaR, s_etaA, s_zeta;
    __shared__ float dR[NA], qfcR[NA];             // radial list, species-sorted
    __shared__ int   cntRspw[NWARP][NS];
    __shared__ int   rstart[NS + 1];
    __shared__ int   wcntA[NWARP];
    __shared__ float avx[NA], avy[NA], avz[NA], ad[NA], afc[NA];
    __shared__ int   asp[NA];
    __shared__ float f1s[CHUNK * 9];               // padded stride 9
    __shared__ float f2s[CHUNK * 5];               // padded stride 5
    __shared__ int   cntPw[NWARP][NPAIRS_SP];

    // ---- phase 0: load (spread across warps) ----
    if (tid < 36)
        ((float4*)scrd)[tid] = ((const float4*)(coords + (size_t)m * NA * 3))[tid];
    if (tid >= 64 && tid < 64 + NA)
        ssp[tid - 64] = species[(size_t)m * NA + (tid - 64)];
    if (tid >= 36 && tid < 52) shfr[tid - 36] = gShfR[tid - 36];
    if (tid >= 52 && tid < 56) shfa[tid - 52] = gShfA[tid - 52];
    if (tid >= 112 && tid < 120) {
        float z = gShfZ[tid - 112];
        cshfz[tid - 112] = cosf(z);
        sshfz[tid - 112] = sinf(z);
    }
    if (tid == 120) s_etaR = gEtaR[0];
    if (tid == 121) s_etaA = gEtaA[0];
    if (tid == 122) s_zeta = gZeta[0];
    __syncthreads();

    const float cx = scrd[i * 3], cy = scrd[i * 3 + 1], cz = scrd[i * 3 + 2];
    const float etaR = s_etaR, etaA = s_etaA, zeta = s_zeta;
    const bool z32 = (zeta == 32.0f);

    // ---- phase 1: compaction, uniform across all 4 warps (warps 2,3 all-invalid) ----
    {
        int j = tid;
        bool valid = (j < NA) && (j != i);
        float dx = 0.f, dy = 0.f, dz = 0.f, d = 1e9f;
        int sp = 0;
        if (valid) {
            dx = scrd[j * 3] - cx;
            dy = scrd[j * 3 + 1] - cy;
            dz = scrd[j * 3 + 2] - cz;
            d = sqrtf(dx * dx + dy * dy + dz * dz);
            sp = ssp[j];
        }
        bool inR = valid && (d <= RCR_F);
        bool inA = valid && (d <= RCA_F);

        unsigned ballA = __ballot_sync(FULLM, inA);
        unsigned myb = 0;
        #pragma unroll
        for (int k = 0; k < NS; k++) {
            unsigned bk = __ballot_sync(FULLM, inR && (sp == k));
            if (lane == k) cntRspw[wid][k] = __popc(bk);
            if (sp == k) myb = bk;
        }
        int rankR = __popc(myb & ltm);
        int rankA = __popc(ballA & ltm);
        if (lane == 0) wcntA[wid] = __popc(ballA);
        __syncthreads();

        // per-warp redundant scan of species counts
        int totL = 0, ownpreL = 0;
        if (lane < NS) {
            int acc = 0;
            #pragma unroll
            for (int w = 0; w < NWARP; w++) {
                int c = cntRspw[w][lane];
                if (w == wid) ownpreL = acc;
                acc += c;
            }
            totL = acc;
        }
        int scan = totL;
        #pragma unroll
        for (int o = 1; o < 8; o <<= 1) {
            int v = __shfl_up_sync(FULLM, scan, o);
            if (lane >= o) scan += v;
        }
        int startL = scan - totL;
        if (wid == 0 && lane <= NS) rstart[lane] = startL;  // lane==NS -> total

        int radoff = __shfl_sync(FULLM, startL + ownpreL, valid ? sp : 0);
        if (inR) {
            int off = radoff + rankR;
            dR[off] = d;
            qfcR[off] = 0.25f * (0.5f * __cosf(d * (PI_F / RCR_F)) + 0.5f);
        }
        int preA = 0;
        #pragma unroll
        for (int w = 0; w < NWARP; w++) if (w < wid) preA += wcntA[w];
        if (inA) {
            int off = preA + rankA;
            avx[off] = dx; avy[off] = dy; avz[off] = dz;
            ad[off] = d;
            afc[off] = 0.5f * __cosf(d * (PI_F / RCA_F)) + 0.5f;
            asp[off] = sp;
        }
    }
    const int nA = wcntA[0] + wcntA[1] + wcntA[2] + wcntA[3];
    __syncthreads();   // lists visible

    // ---- phase 2: angular pairs, chunked; per-warp redundant scans ----
    const int npairs = nA * (nA - 1) / 2;
    const int s0 = (tid >> 3) & 3, t0 = tid & 7;
    float acc0 = 0.f, acc1 = 0.f, acc2 = 0.f;

    for (int base = 0; base < npairs; base += CHUNK) {
        if (base > 0) __syncthreads();   // protect previous chunk's scan

        int p = base + tid;
        bool pvalid = (p < npairs);
        int a = 0, b = 0, pidx = NPAIRS_SP;
        if (pvalid) {
            decode_pair(p, nA, a, b);
            pidx = triu_idx(asp[a], asp[b]);
        }

        unsigned msk = __match_any_sync(FULLM, pidx);
        int rank = __popc(msk & ltm);
        #pragma unroll
        for (int k = 0; k < NPAIRS_SP; k++) {
            unsigned bk = __ballot_sync(FULLM, pidx == k);
            if (lane == k) cntPw[wid][k] = __popc(bk);
        }
        __syncthreads();

        // every warp: scan of cntPw over warps + bucket starts, all in registers
        int totP = 0, ownpreP = 0;
        if (lane < NPAIRS_SP) {
            int acc = 0;
            #pragma unroll
            for (int w = 0; w < NWARP; w++) {
                int c = cntPw[w][lane];
                if (w == wid) ownpreP = acc;
                acc += c;
            }
            totP = acc;
        }
        int scan = totP;
        #pragma unroll
        for (int o = 1; o < 16; o <<= 1) {
            int v = __shfl_up_sync(FULLM, scan, o);
            if (lane >= o) scan += v;
        }
        int startP = scan - totP;
        int endP = scan;

        int slotbase = __shfl_sync(FULLM, startP + ownpreP, pvalid ? pidx : 0);
        if (pvalid) {
            int slot = slotbase + rank;

            float d1 = ad[a], d2 = ad[b];
            float dot = avx[a] * avx[b] + avy[a] * avy[b] + avz[a] * avz[b];
            float cosv = 0.95f * __fdividef(dot, fmaxf(d1, 1e-8f) * fmaxf(d2, 1e-8f));
            float sinv = sqrtf(fmaxf(1.0f - cosv * cosv, 0.0f));
            float dm = 0.5f * (d1 + d2);
            float fcj2 = 2.0f * afc[a] * afc[b];

            #pragma unroll
            for (int t = 0; t < NSHFZ; t++) {
                float c = cosv * cshfz[t] + sinv * sshfz[t];
                float bse = 0.5f * (1.0f + c);
                f1s[slot * 9 + t] = pow_zeta(bse, zeta, z32) * fcj2;
            }
            #pragma unroll
            for (int s = 0; s < NSHFA; s++) {
                float dd = dm - shfa[s];
                f2s[slot * 5 + s] = __expf(-etaA * dd * dd);
            }
        }
        __syncthreads();

        // feature accumulation: warp w scans bucket w, then 4+w; warps 0,1: 8,9
        {
            int qb = __shfl_sync(FULLM, startP, wid);
            int qe = __shfl_sync(FULLM, endP, wid);
            for (int q = qb; q < qe; q++)
                acc0 += f1s[q * 9 + t0] * f2s[q * 5 + s0];
        }
        {
            int qb = __shfl_sync(FULLM, startP, 4 + wid);
            int qe = __shfl_sync(FULLM, endP, 4 + wid);
            for (int q = qb; q < qe; q++)
                acc1 += f1s[q * 9 + t0] * f2s[q * 5 + s0];
        }
        if (wid < 2) {
            int qb = __shfl_sync(FULLM, startP, 8 + wid);
            int qe = __shfl_sync(FULLM, endP, 8 + wid);
            for (int q = qb; q < qe; q++)
                acc2 += f1s[q * 9 + t0] * f2s[q * 5 + s0];
        }
    }

    // ---- phase 3: radial (registers -> gmem) + angular writeout; no sync needed ----
    float* o = out + ((size_t)m * NA + i) * AEV_LEN;
    if (tid < RAD_FEAT) {
        int sp = tid >> 4;
        float sk = shfr[tid & 15];
        float acc = 0.0f;
        int jb = rstart[sp], je = rstart[sp + 1];
        for (int j = jb; j < je; j++) {
            float t = dR[j] - sk;
            acc += qfcR[j] * __expf(-etaR * t * t);
        }
        o[tid] = acc;
    }
    o[RAD_FEAT + tid] = acc0;
    o[RAD_FEAT + 128 + tid] = acc1;
    if (tid < 64) o[RAD_FEAT + 256 + tid] = acc2;
}

extern "C" void kernel_launch(void* const* d_in, const int* in_sizes, int n_in,
                              void* d_out, int out_size) {
    const float* coords = (const float*)d_in[0];
    const float* EtaR   = (const float*)d_in[1];
    const float* ShfR   = (const float*)d_in[2];
    const float* EtaA   = (const float*)d_in[3];
    const float* Zeta   = (const float*)d_in[4];
    const float* ShfA   = (const float*)d_in[5];
    const float* ShfZ   = (const float*)d_in[6];
    const int*   spec   = (const int*)d_in[7];
    float* out = (float*)d_out;

    int MA = in_sizes[7];
    int M = MA / NA;

    dim3 grid(NA, M);
    aev_kernel<<<grid, NTHR>>>(coords, EtaR, ShfR, EtaA, Zeta, ShfA, ShfZ, spec, out);
}